// round 1
// baseline (speedup 1.0000x reference)
#include <cuda_runtime.h>

#define NBATCH 8192
#define NPTS   128
#define NHID   128
#define NCH    32
#define NLAT   16
#define TPB    256

// dynamic shared memory layout (bytes)
#define O_W2 0          // 128*128 f32 = 65536
#define O_H  65536      // 128*129 f32 = 66048 (padded rows)
#define O_W3 131584     // 128*32 f32  = 16384
#define O_WP 147968     // 32*128 f32  = 16384 (fspool weights)
#define O_W1 164352     // 4*128 f32   = 2048
#define O_X  166400     // 128*4 f32   = 2048
#define O_B1 168448     // 512
#define O_B2 168960     // 512
#define O_B3 169472     // 128
#define O_PL 169600     // 128 (pooled)
#define SMEM_BYTES 169728
// aliases (used after their hosts are dead):
#define O_KEY 0         // u32[32*128] = 16384  (aliases W2)
#define O_ZC  16384     // f32[32*128] = 16384  (aliases W2)
#define O_ZT  65536     // f32[128*33] = 16896  (aliases H)

typedef unsigned long long ull;

__device__ __forceinline__ ull pk2(float lo, float hi) {
    ull r; asm("mov.b64 %0, {%1,%2};" : "=l"(r) : "f"(lo), "f"(hi)); return r;
}
__device__ __forceinline__ float2 upk2(ull v) {
    float2 r; asm("mov.b64 {%0,%1}, %2;" : "=f"(r.x), "=f"(r.y) : "l"(v)); return r;
}
#define FMA2(d,a,b,c) asm("fma.rn.f32x2 %0, %1, %2, %3;" : "=l"(d) : "l"(a), "l"(b), "l"(c))

__global__ __launch_bounds__(TPB, 1)
void enc_kernel(const float* __restrict__ x,  const float* __restrict__ W1,
                const float* __restrict__ b1, const float* __restrict__ W2,
                const float* __restrict__ b2, const float* __restrict__ W3,
                const float* __restrict__ b3, const float* __restrict__ pwm,
                const float* __restrict__ eps, float* __restrict__ out)
{
    extern __shared__ __align__(16) char smem[];
    const int tid = threadIdx.x;
    const int b = blockIdx.x;

    // ------------------- stage to shared -------------------
    {
        const float4* g4 = (const float4*)W2;
        float4* s4 = (float4*)(smem + O_W2);
        for (int i = tid; i < 4096; i += TPB) s4[i] = g4[i];
        g4 = (const float4*)W3; s4 = (float4*)(smem + O_W3);
        for (int i = tid; i < 1024; i += TPB) s4[i] = g4[i];
        if (tid < 128) {
            ((float4*)(smem + O_W1))[tid] = ((const float4*)W1)[tid];
            ((float4*)(smem + O_X ))[tid] = ((const float4*)(x + (size_t)b * 512))[tid];
        }
        if (tid >= 128 && tid < 160) ((float4*)(smem + O_B1))[tid-128] = ((const float4*)b1)[tid-128];
        if (tid >= 160 && tid < 192) ((float4*)(smem + O_B2))[tid-160] = ((const float4*)b2)[tid-160];
        if (tid >= 192 && tid < 200) ((float4*)(smem + O_B3))[tid-192] = ((const float4*)b3)[tid-192];
        // fspool weights: w[c][p] = (1-frac)*pw[c][idx] + frac*pw[c][idx+1]
        float* sWp = (float*)(smem + O_WP);
        for (int i = tid; i < 4096; i += TPB) {
            int c = i >> 7, pp = i & 127;
            float pos = (float)pp / 127.0f * 20.0f;
            int idx = (int)pos; if (idx > 20) idx = 20;
            float frac = pos - (float)idx;
            int idx2 = idx + 1; if (idx2 > 20) idx2 = 20;
            sWp[i] = (1.0f - frac) * pwm[c*21 + idx] + frac * pwm[c*21 + idx2];
        }
    }
    __syncthreads();

    const int p = tid & 127;
    const int half = tid >> 7;

    // ------------------- layer 1 -------------------
    {
        float* sH = (float*)(smem + O_H);
        const float* sW1 = (const float*)(smem + O_W1);
        const float* sX  = (const float*)(smem + O_X);
        const float* sb1 = (const float*)(smem + O_B1);
        float x0 = sX[p*4+0], x1 = sX[p*4+1], x2 = sX[p*4+2], x3 = sX[p*4+3];
        const int j0 = half * 64;
        #pragma unroll 8
        for (int j = j0; j < j0 + 64; j++) {
            float a = sb1[j];
            a = fmaf(x0, sW1[j],       a);
            a = fmaf(x1, sW1[128 + j], a);
            a = fmaf(x2, sW1[256 + j], a);
            a = fmaf(x3, sW1[384 + j], a);
            sH[p*129 + j] = fmaxf(a, 0.0f);
        }
    }
    __syncthreads();

    // ------------------- layer 2 + layer 3 (fused) -------------------
    // thread (p, half) handles point p, k in [half*64, half*64+64)
    ull zacc[16];
    {
        const float* sW2f = (const float*)(smem + O_W2);
        const float* sW3f = (const float*)(smem + O_W3);
        const float* sb2  = (const float*)(smem + O_B2);
        const float* sb3  = (const float*)(smem + O_B3);
        const float* sH   = (const float*)(smem + O_H);

        #pragma unroll
        for (int m = 0; m < 16; m++)
            zacc[m] = (half == 0) ? pk2(sb3[2*m], sb3[2*m+1]) : 0ull;

        const int kbase = half * 64;
        const float* hrow = sH + p * 129;
        for (int kb = 0; kb < 8; kb++) {
            const int k0 = kbase + kb * 8;
            ull a0 = pk2(sb2[k0+0], sb2[k0+1]);
            ull a1 = pk2(sb2[k0+2], sb2[k0+3]);
            ull a2 = pk2(sb2[k0+4], sb2[k0+5]);
            ull a3 = pk2(sb2[k0+6], sb2[k0+7]);
            #pragma unroll 4
            for (int j = 0; j < 128; j++) {
                float h = hrow[j];
                ull h2 = pk2(h, h);
                const ulonglong2* wr = (const ulonglong2*)(sW2f + j * 128 + k0);
                ulonglong2 wa = wr[0];
                ulonglong2 wb = wr[1];
                FMA2(a0, h2, wa.x, a0);
                FMA2(a1, h2, wa.y, a1);
                FMA2(a2, h2, wb.x, a2);
                FMA2(a3, h2, wb.y, a3);
            }
            float hv[8]; float2 t;
            t = upk2(a0); hv[0] = fmaxf(t.x, 0.f); hv[1] = fmaxf(t.y, 0.f);
            t = upk2(a1); hv[2] = fmaxf(t.x, 0.f); hv[3] = fmaxf(t.y, 0.f);
            t = upk2(a2); hv[4] = fmaxf(t.x, 0.f); hv[5] = fmaxf(t.y, 0.f);
            t = upk2(a3); hv[6] = fmaxf(t.x, 0.f); hv[7] = fmaxf(t.y, 0.f);
            #pragma unroll
            for (int i = 0; i < 8; i++) {
                ull hk2 = pk2(hv[i], hv[i]);
                const ulonglong2* w3r = (const ulonglong2*)(sW3f + (k0 + i) * 32);
                #pragma unroll
                for (int q = 0; q < 8; q++) {
                    ulonglong2 w = w3r[q];
                    FMA2(zacc[2*q],   hk2, w.x, zacc[2*q]);
                    FMA2(zacc[2*q+1], hk2, w.y, zacc[2*q+1]);
                }
            }
        }
    }
    __syncthreads();   // all reads of sH / sW2 complete

    // ------------------- combine halves, build sort keys -------------------
    {
        float z[32];
        #pragma unroll
        for (int m = 0; m < 16; m++) { float2 t = upk2(zacc[m]); z[2*m] = t.x; z[2*m+1] = t.y; }

        float* sZt = (float*)(smem + O_ZT);
        if (half == 1) {
            #pragma unroll
            for (int c = 0; c < 32; c++) sZt[p*33 + c] = z[c];
        }
        __syncthreads();
        unsigned* sKey = (unsigned*)(smem + O_KEY);
        float* sZc = (float*)(smem + O_ZC);
        if (half == 0) {
            #pragma unroll
            for (int c = 0; c < 32; c++) {
                float zv = z[c] + sZt[p*33 + c];
                sZc[c*128 + p] = zv;
                unsigned u = __float_as_uint(zv);
                unsigned s = (u & 0x80000000u) ? ~u : (u | 0x80000000u);
                // truncate 7 LSBs, embed index -> all 128 keys distinct (exact permutation)
                sKey[c*128 + p] = (s & 0xFFFFFF80u) | (unsigned)(127 - p);
            }
        }
    }
    __syncthreads();

    // ------------------- ranking + weighted pool -------------------
    {
        const unsigned* sKey = (const unsigned*)(smem + O_KEY);
        const float* sZc = (const float*)(smem + O_ZC);
        const float* sWp = (const float*)(smem + O_WP);
        float* sPl = (float*)(smem + O_PL);
        const int w = tid >> 5, lane = tid & 31;
        for (int cc = 0; cc < 4; cc++) {
            const int c = w * 4 + cc;
            const unsigned* kp = sKey + c * 128;
            const float* zp = sZc + c * 128;
            unsigned k0 = kp[lane], k1 = kp[lane+32], k2 = kp[lane+64], k3 = kp[lane+96];
            int r0 = 0, r1 = 0, r2 = 0, r3 = 0;
            const uint4* kq4 = (const uint4*)kp;
            #pragma unroll 4
            for (int qq = 0; qq < 32; qq++) {
                uint4 kq = kq4[qq];
                r0 += (kq.x > k0) + (kq.y > k0) + (kq.z > k0) + (kq.w > k0);
                r1 += (kq.x > k1) + (kq.y > k1) + (kq.z > k1) + (kq.w > k1);
                r2 += (kq.x > k2) + (kq.y > k2) + (kq.z > k2) + (kq.w > k2);
                r3 += (kq.x > k3) + (kq.y > k3) + (kq.z > k3) + (kq.w > k3);
            }
            const float* wc = sWp + c * 128;
            float sum = zp[lane]    * wc[r0]
                      + zp[lane+32] * wc[r1]
                      + zp[lane+64] * wc[r2]
                      + zp[lane+96] * wc[r3];
            #pragma unroll
            for (int ofs = 16; ofs > 0; ofs >>= 1)
                sum += __shfl_xor_sync(0xffffffffu, sum, ofs);
            if (lane == 0) sPl[c] = sum;
        }
    }
    __syncthreads();

    // ------------------- reparameterize + write -------------------
    if (tid < 16) {
        const float* sPl = (const float*)(smem + O_PL);
        float mu = sPl[2*tid];
        float lv = sPl[2*tid + 1];
        float e  = eps[(size_t)b*16 + tid];
        float smp = fmaf(e, expf(0.5f * lv), mu);
        out[(size_t)b*16 + tid] = mu;
        out[(size_t)(NBATCH*NLAT)   + (size_t)b*16 + tid] = lv;
        out[(size_t)(2*NBATCH*NLAT) + (size_t)b*16 + tid] = smp;
    }
}

extern "C" void kernel_launch(void* const* d_in, const int* in_sizes, int n_in,
                              void* d_out, int out_size) {
    const float* x   = (const float*)d_in[0];
    const float* W1  = (const float*)d_in[1];
    const float* b1  = (const float*)d_in[2];
    const float* W2  = (const float*)d_in[3];
    const float* b2  = (const float*)d_in[4];
    const float* W3  = (const float*)d_in[5];
    const float* b3  = (const float*)d_in[6];
    const float* pwm = (const float*)d_in[7];
    const float* eps = (const float*)d_in[8];
    float* out = (float*)d_out;

    cudaFuncSetAttribute(enc_kernel, cudaFuncAttributeMaxDynamicSharedMemorySize, SMEM_BYTES);
    enc_kernel<<<NBATCH, TPB, SMEM_BYTES>>>(x, W1, b1, W2, b2, W3, b3, pwm, eps, out);
}